// round 16
// baseline (speedup 1.0000x reference)
#include <cuda_runtime.h>
#include <cuda_fp16.h>
#include <cstdint>

#define BB 8
#define EE 2048
#define NN 2048
#define FF 128

// Y^T scratch: [b][f][node], fp16 (4 MiB). node contiguous -> B-fragment K-pairs.
__device__ __half g_Yt[BB * FF * NN];

// ---------------- helpers ----------------
__device__ __forceinline__ uint32_t smem_u32(const void* p) {
    uint32_t a;
    asm("{ .reg .u64 t; cvta.to.shared.u64 t, %1; cvt.u32.u64 %0, t; }"
        : "=r"(a) : "l"(p));
    return a;
}
__device__ __forceinline__ uint32_t f2tf32(float x) {
    uint32_t r;
    asm("cvt.rna.tf32.f32 %0, %1;" : "=r"(r) : "f"(x));
    return r;
}
__device__ __forceinline__ void mma_tf32(float d[4], const uint32_t a[4],
                                         const uint32_t b[2], const float c[4]) {
    asm volatile(
        "mma.sync.aligned.m16n8k8.row.col.f32.tf32.tf32.f32 "
        "{%0,%1,%2,%3}, {%4,%5,%6,%7}, {%8,%9}, {%10,%11,%12,%13};"
        : "=f"(d[0]), "=f"(d[1]), "=f"(d[2]), "=f"(d[3])
        : "r"(a[0]), "r"(a[1]), "r"(a[2]), "r"(a[3]),
          "r"(b[0]), "r"(b[1]),
          "f"(c[0]), "f"(c[1]), "f"(c[2]), "f"(c[3]));
}
__device__ __forceinline__ void mma_f16(float d[4], const uint32_t a[4],
                                        const uint32_t b0, const uint32_t b1,
                                        const float c[4]) {
    asm volatile(
        "mma.sync.aligned.m16n8k16.row.col.f32.f16.f16.f32 "
        "{%0,%1,%2,%3}, {%4,%5,%6,%7}, {%8,%9}, {%10,%11,%12,%13};"
        : "=f"(d[0]), "=f"(d[1]), "=f"(d[2]), "=f"(d[3])
        : "r"(a[0]), "r"(a[1]), "r"(a[2]), "r"(a[3]),
          "r"(b0), "r"(b1),
          "f"(c[0]), "f"(c[1]), "f"(c[2]), "f"(c[3]));
}
__device__ __forceinline__ void ldsm_x4(uint32_t& d0, uint32_t& d1,
                                        uint32_t& d2, uint32_t& d3, uint32_t addr) {
    asm volatile("ldmatrix.sync.aligned.m8n8.x4.shared.b16 {%0,%1,%2,%3}, [%4];"
                 : "=r"(d0), "=r"(d1), "=r"(d2), "=r"(d3) : "r"(addr));
}
__device__ __forceinline__ void cpa16(uint32_t s, const void* g) {
    asm volatile("cp.async.cg.shared.global [%0], [%1], 16;" :: "r"(s), "l"(g));
}
__device__ __forceinline__ void cpa_commit() { asm volatile("cp.async.commit_group;"); }
template <int W> __device__ __forceinline__ void cpa_wait() {
    asm volatile("cp.async.wait_group %0;" :: "n"(W));
}

#define MBAR_INIT(addr, cnt) \
    asm volatile("mbarrier.init.shared.b64 [%0], %1;" :: "r"((uint32_t)(addr)), "r"((uint32_t)(cnt)) : "memory")
#define MBAR_ARRIVE(addr) \
    asm volatile("mbarrier.arrive.shared.b64 _, [%0];" :: "r"((uint32_t)(addr)) : "memory")
#define MBAR_WAIT(addr, ph) do {                                                     \
    uint32_t _a = (uint32_t)(addr), _p = (uint32_t)(ph);                             \
    asm volatile("{\n\t.reg .pred P;\n\t"                                            \
        "WL%=:\n\t"                                                                  \
        "mbarrier.try_wait.parity.acquire.cta.shared::cta.b64 P, [%0], %1, 0x989680;\n\t" \
        "@P bra.uni WD%=;\n\t"                                                       \
        "bra.uni WL%=;\n\t"                                                          \
        "WD%=:\n\t}" :: "r"(_a), "r"(_p) : "memory");                                \
} while (0)
#define CP_MBAR_ARRIVE(addr) \
    asm volatile("cp.async.mbarrier.arrive.shared::cta.b64 [%0];" :: "r"((uint32_t)(addr)) : "memory")

// half2 {1.0 or 0.0, 1.0 or 0.0} from 2 mask bits (bit0 -> lo, bit1 -> hi)
__device__ __forceinline__ uint32_t pair_h2(uint32_t v2) {
    return ((v2 & 1u) * 0x3C00u) | ((v2 >> 1) * 0x3C000000u);
}

// ---------------- Kernel A: Yt = fp16(W @ X^T) per batch ----------------
#define A_SMEM_BYTES ((64 + 128) * 132 * 4)

__global__ __launch_bounds__(256, 2) void k_xw(const float* __restrict__ X,
                                               const float* __restrict__ W) {
    extern __shared__ float sm[];
    float* sX = sm;              // [64][132]   node rows
    float* sW = sm + 64 * 132;   // [128][132]  f rows
    const int tid = threadIdx.x;
    const long rbase = (long)blockIdx.x * 64;      // b*2048 + nbase
    const int b = (int)(rbase >> 11);
    const int nbase = (int)(rbase & 2047);

    uint32_t sXb = (uint32_t)__cvta_generic_to_shared(sX);
    uint32_t sWb = (uint32_t)__cvta_generic_to_shared(sW);

#pragma unroll
    for (int i = 0; i < 8; ++i) {
        int id = tid + i * 256;
        int r = id >> 5;
        int c4 = (id & 31) * 4;
        cpa16(sXb + (uint32_t)(r * 132 + c4) * 4, X + (rbase + r) * FF + c4);
    }
#pragma unroll
    for (int i = 0; i < 16; ++i) {
        int id = tid + i * 256;
        int r = id >> 5;
        int c4 = (id & 31) * 4;
        cpa16(sWb + (uint32_t)(r * 132 + c4) * 4, W + r * FF + c4);
    }
    cpa_commit();
    cpa_wait<0>();
    __syncthreads();

    const int lane = tid & 31, warp = tid >> 5;
    const int wm = warp >> 1, wn = warp & 1;
    const int gid = lane >> 2, tig = lane & 3;

    float acc[2][4][4];
#pragma unroll
    for (int mt = 0; mt < 2; ++mt)
#pragma unroll
        for (int nt = 0; nt < 4; ++nt)
#pragma unroll
            for (int j = 0; j < 4; ++j) acc[mt][nt][j] = 0.f;

#pragma unroll
    for (int ks = 0; ks < 16; ++ks) {
        const int k0 = ks * 8;
        uint32_t af[2][4];
#pragma unroll
        for (int mt = 0; mt < 2; ++mt) {          // A rows = f, from sW
            int f = wm * 32 + mt * 16 + gid;
            af[mt][0] = f2tf32(sW[f * 132 + k0 + tig]);
            af[mt][1] = f2tf32(sW[(f + 8) * 132 + k0 + tig]);
            af[mt][2] = f2tf32(sW[f * 132 + k0 + tig + 4]);
            af[mt][3] = f2tf32(sW[(f + 8) * 132 + k0 + tig + 4]);
        }
        uint32_t bf[4][2];
#pragma unroll
        for (int nt = 0; nt < 4; ++nt) {          // B rows = nodes, from sX
            int n = wn * 32 + nt * 8 + gid;
            bf[nt][0] = f2tf32(sX[n * 132 + k0 + tig]);
            bf[nt][1] = f2tf32(sX[n * 132 + k0 + tig + 4]);
        }
#pragma unroll
        for (int mt = 0; mt < 2; ++mt)
#pragma unroll
            for (int nt = 0; nt < 4; ++nt)
                mma_tf32(acc[mt][nt], af[mt], bf[nt], acc[mt][nt]);
    }

    // store Yt[b][f][node] as fp16 (half2 per thread: adjacent nodes)
    __half* Ybase = g_Yt + (long)b * FF * NN;
#pragma unroll
    for (int mt = 0; mt < 2; ++mt)
#pragma unroll
        for (int h = 0; h < 2; ++h) {
            int f = wm * 32 + mt * 16 + gid + 8 * h;
#pragma unroll
            for (int nt = 0; nt < 4; ++nt) {
                int n0 = wn * 32 + nt * 8 + 2 * tig;
                __half2 hv = __floats2half2_rn(acc[mt][nt][2 * h + 0],
                                               acc[mt][nt][2 * h + 1]);
                *(__half2*)&Ybase[(long)f * NN + nbase + n0] = hv;
            }
        }
}

// ---------------- Kernel B: fp16 warp-specialized pipelined masked GEMM ----------------
// 384 threads: warps 0-7 consumers (2x4 grid: M=32, N=32 each; acc=32 regs),
//              warps 8-11 producers.
// Producer warp pw owns edge rows pw*16..+15 and expands the A fragments for
// that row-group ONCE (R14-proven mapping). Ballot words are warp-uniform, so
// lane 0 stores all 16 rows to a per-warp scratch and expansion lanes read
// them back (kills the 96-instr lane-select chain). Consumers: pure
// LDS.128 + ldmatrix + HMMA -- zero ALU in the hot loop.
#define KC 64
#define Y_ROW 144
#define NSTG 4
#define STG_Y (128 * Y_ROW)                  // 18432
#define STG_A 8192                           // [t4][group4][lane32] x 16B
#define OFF_Y 0
#define OFF_A (NSTG * STG_Y)                 // 73728
#define OFF_MS (OFF_A + NSTG * STG_A)        // 106496: mask scratch 64 rows x 8B
#define OFF_CNT (OFF_MS + 512)               // 107008
#define OFF_FULL (OFF_CNT + 256)             // 107264
#define OFF_EMPTY (OFF_FULL + NSTG * 8)      // 107296
#define OFF_DONE (OFF_EMPTY + NSTG * 8)      // 107328
#define B_SMEM_BYTES (OFF_DONE + 8)          // 107336

__global__ __launch_bounds__(384, 2) void k_agg(const float* __restrict__ adj,
                                                const float* __restrict__ bias,
                                                float* __restrict__ out) {
    extern __shared__ char smc[];
    const uint32_t sb = smem_u32(smc);
    const int tid = threadIdx.x, wid = tid >> 5, lane = tid & 31;
    const int eb = blockIdx.x * 64, b = blockIdx.y;
    const float* adjBase = adj + ((long)b * EE + eb) * NN;
    const __half* Ytb = g_Yt + (long)b * FF * NN;

    if (tid == 0) {
#pragma unroll
        for (int i = 0; i < NSTG; ++i) {
            MBAR_INIT(sb + OFF_FULL + i * 8, 4);     // 4 producer leaders (+cp self-balance)
            MBAR_INIT(sb + OFF_EMPTY + i * 8, 8);    // 8 consumer leaders
        }
        MBAR_INIT(sb + OFF_DONE, 4);
    }
    __syncthreads();

    if (wid >= 8) {
        // ===================== producer =====================
        const int p = tid - 256;            // 0..127
        const int pw = p >> 5, pl = p & 31; // warp pw owns edge rows pw*16..+15
        const int egid = pl >> 2, etig = pl & 3;
        const float* arow = adjBase + (long)(pw * 16) * NN + pl;
        const uint32_t msbase = sb + OFF_MS + (uint32_t)(pw * 16) * 8;
        int cnt = 0;                        // lane i<16: count for row pw*16+i
        int slot = 0, ph = 1;               // producer starts phase-flipped

#pragma unroll 1
        for (int s = 0; s < NN / KC; ++s) {
            MBAR_WAIT(sb + OFF_EMPTY + slot * 8, ph);

            // Y tile via cp.async: thread p owns f-row p (128 B)
            {
                const char* ysrc = (const char*)(Ytb + (long)p * NN + s * KC);
                uint32_t ydst = sb + OFF_Y + slot * STG_Y + (uint32_t)p * Y_ROW;
#pragma unroll
                for (int j = 0; j < 8; ++j)
                    cpa16(ydst + j * 16, ysrc + j * 16);
            }
            CP_MBAR_ARRIVE(sb + OFF_FULL + slot * 8);

            // adj chunk: issue all 32 loads (MLP), then ballots
            float v0[16], v1[16];
            const float* ac = arow + s * KC;
#pragma unroll
            for (int i = 0; i < 16; ++i) {
                v0[i] = ac[(long)i * NN];
                v1[i] = ac[(long)i * NN + 32];
            }
            // ballots are warp-uniform: lane 0 stores each row's 2 words
#pragma unroll
            for (int i = 0; i < 16; ++i) {
                uint32_t m0 = __ballot_sync(0xffffffffu, v0[i] == -1.f);
                uint32_t m1 = __ballot_sync(0xffffffffu, v1[i] == -1.f);
                if (pl == 0)
                    asm volatile("st.shared.v2.b32 [%0], {%1,%2};"
                                 :: "r"(msbase + (uint32_t)i * 8), "r"(m0), "r"(m1));
            }
            __syncwarp();

            // counts (lane i<16 reads its row back)
            if (pl < 16) {
                uint32_t w0, w1;
                asm volatile("ld.shared.v2.b32 {%0,%1}, [%2];"
                             : "=r"(w0), "=r"(w1) : "r"(msbase + (uint32_t)pl * 8));
                cnt += __popc(w0) + __popc(w1);
            }

            // expansion (R14 mapping): rows egid, egid+8 of this group
            uint32_t r0h0, r0h1, r1h0, r1h1;
            asm volatile("ld.shared.v2.b32 {%0,%1}, [%2];"
                         : "=r"(r0h0), "=r"(r0h1) : "r"(msbase + (uint32_t)egid * 8));
            asm volatile("ld.shared.v2.b32 {%0,%1}, [%2];"
                         : "=r"(r1h0), "=r"(r1h1) : "r"(msbase + (uint32_t)(egid + 8) * 8));
            uint32_t abase = sb + OFF_A + slot * STG_A + (uint32_t)(pw * 32 + pl) * 16;
#pragma unroll
            for (int t = 0; t < 4; ++t) {
                uint32_t w0 = (t < 2) ? r0h0 : r0h1;
                uint32_t w1 = (t < 2) ? r1h0 : r1h1;
                int sh = (t & 1) * 16 + 2 * etig;
                uint32_t a0 = pair_h2((w0 >> sh) & 3u);
                uint32_t a1 = pair_h2((w1 >> sh) & 3u);
                uint32_t a2 = pair_h2((w0 >> (sh + 8)) & 3u);
                uint32_t a3 = pair_h2((w1 >> (sh + 8)) & 3u);
                asm volatile("st.shared.v4.b32 [%0], {%1,%2,%3,%4};"
                             :: "r"(abase + (uint32_t)t * 2048),
                                "r"(a0), "r"(a1), "r"(a2), "r"(a3));
            }
            __syncwarp();
            if (pl == 0) MBAR_ARRIVE(sb + OFF_FULL + slot * 8);

            if (++slot == NSTG) { slot = 0; ph ^= 1; }
        }

        // publish per-row counts once
        if (pl < 16) ((int*)(smc + OFF_CNT))[pw * 16 + pl] = cnt;
        __syncwarp();
        if (pl == 0) MBAR_ARRIVE(sb + OFF_DONE);
    } else {
        // ===================== consumer =====================
        const int wm = wid & 1, wn = wid >> 1;    // M-half, N-block
        const int gid = lane >> 2, tig = lane & 3;

        float acc[2][4][4];
#pragma unroll
        for (int mt = 0; mt < 2; ++mt)
#pragma unroll
            for (int nt = 0; nt < 4; ++nt)
#pragma unroll
                for (int j = 0; j < 4; ++j) acc[mt][nt][j] = 0.f;

        const uint32_t lm1 = (uint32_t)((wn * 32 + ((lane >> 4) & 1) * 8 + (lane & 7)) * Y_ROW +
                                        ((lane >> 3) & 1) * 16);
        const uint32_t lm2 = lm1 + 16 * Y_ROW;
        const uint32_t aoff0 = (uint32_t)((wm * 2 + 0) * 32 + lane) * 16;
        const uint32_t aoff1 = (uint32_t)((wm * 2 + 1) * 32 + lane) * 16;
        int slot = 0, ph = 0;

#pragma unroll 1
        for (int s = 0; s < NN / KC; ++s) {
            MBAR_WAIT(sb + OFF_FULL + slot * 8, ph);

            const uint32_t yb = sb + OFF_Y + slot * STG_Y;
            const uint32_t ab = sb + OFF_A + slot * STG_A;
#pragma unroll
            for (int t = 0; t < 4; ++t) {
                uint32_t a0[4], a1[4];
                asm volatile("ld.shared.v4.b32 {%0,%1,%2,%3}, [%4];"
                             : "=r"(a0[0]), "=r"(a0[1]), "=r"(a0[2]), "=r"(a0[3])
                             : "r"(ab + (uint32_t)t * 2048 + aoff0));
                asm volatile("ld.shared.v4.b32 {%0,%1,%2,%3}, [%4];"
                             : "=r"(a1[0]), "=r"(a1[1]), "=r"(a1[2]), "=r"(a1[3])
                             : "r"(ab + (uint32_t)t * 2048 + aoff1));
                uint32_t b01[4], b23[4];
                ldsm_x4(b01[0], b01[1], b01[2], b01[3], yb + (uint32_t)t * 32 + lm1);
                ldsm_x4(b23[0], b23[1], b23[2], b23[3], yb + (uint32_t)t * 32 + lm2);
                mma_f16(acc[0][0], a0, b01[0], b01[1], acc[0][0]);
                mma_f16(acc[0][1], a0, b01[2], b01[3], acc[0][1]);
                mma_f16(acc[0][2], a0, b23[0], b23[1], acc[0][2]);
                mma_f16(acc[0][3], a0, b23[2], b23[3], acc[0][3]);
                mma_f16(acc[1][0], a1, b01[0], b01[1], acc[1][0]);
                mma_f16(acc[1][1], a1, b01[2], b01[3], acc[1][1]);
                mma_f16(acc[1][2], a1, b23[0], b23[1], acc[1][2]);
                mma_f16(acc[1][3], a1, b23[2], b23[3], acc[1][3]);
            }
            __syncwarp();
            if (lane == 0) MBAR_ARRIVE(sb + OFF_EMPTY + slot * 8);

            if (++slot == NSTG) { slot = 0; ph ^= 1; }
        }

        // wait for producer-published counts
        MBAR_WAIT(sb + OFF_DONE, 0);

        // epilogue: row r = wm*32 + mt*16 + gid + 8h
        const int* sCnt = (const int*)(smc + OFF_CNT);
#pragma unroll
        for (int mt = 0; mt < 2; ++mt)
#pragma unroll
            for (int h = 0; h < 2; ++h) {
                int r = wm * 32 + mt * 16 + gid + 8 * h;
                float c = (float)sCnt[r];
                float inv = (c > 0.f) ? (1.f / c) : 1.f;
#pragma unroll
                for (int nt = 0; nt < 4; ++nt) {
                    int cidx = wn * 32 + nt * 8 + 2 * tig;
                    float2 bv = *(const float2*)&bias[cidx];
                    float v0 = fmaxf(acc[mt][nt][2 * h + 0] * inv + bv.x, 0.f);
                    float v1 = fmaxf(acc[mt][nt][2 * h + 1] * inv + bv.y, 0.f);
                    *(float2*)&out[((long)b * EE + eb + r) * FF + cidx] =
                        make_float2(v0, v1);
                }
            }
    }
}

// ---------------- launch ----------------
extern "C" void kernel_launch(void* const* d_in, const int* in_sizes, int n_in,
                              void* d_out, int out_size) {
    const float* X = (const float*)d_in[0];     // node_embeddings [B,N,F]
    const float* adj = (const float*)d_in[1];   // adj [B,E,N]
    const float* W = (const float*)d_in[2];     // W [F,F]
    const float* bias = (const float*)d_in[3];  // b [F]
    float* out = (float*)d_out;

    cudaFuncSetAttribute(k_xw, cudaFuncAttributeMaxDynamicSharedMemorySize, A_SMEM_BYTES);
    cudaFuncSetAttribute(k_agg, cudaFuncAttributeMaxDynamicSharedMemorySize, B_SMEM_BYTES);

    k_xw<<<(BB * NN) / 64, 256, A_SMEM_BYTES>>>(X, W);
    k_agg<<<dim3(EE / 64, BB), 384, B_SMEM_BYTES>>>(adj, bias, out);
}